// round 12
// baseline (speedup 1.0000x reference)
#include <cuda_runtime.h>
#include <cuda_bf16.h>
#include <math.h>
#include <stdint.h>

#define NN   50000
#define EE   800000
#define DIM  128
#define HH   8
#define HID  512
#define CATD 512

typedef __nv_bfloat16 bf16;

// ---------------- static scratch ----------------
__device__ float g_h[(size_t)NN * DIM];
__device__ float g_su[(size_t)NN * HH];
__device__ float g_sv[(size_t)NN * HH];
__device__ float g_ex[(size_t)EE * HH];
__device__ float g_outdeg[NN];
__device__ int   g_count[NN];
__device__ int   g_offsets[NN + 1];
__device__ int   g_cursor[NN];
__device__ int2  g_csr2[EE];
__device__ int   g_bsum[64];
__device__ float g_cw[16 * DIM];
__device__ float g_cb[16];

// bf16 hi/lo operand storage
__device__ bf16 g_x16h[(size_t)NN * DIM],  g_x16l[(size_t)NN * DIM];
__device__ bf16 g_cath[(size_t)NN * CATD], g_catl[(size_t)NN * CATD];
__device__ bf16 g_fh[(size_t)NN * HID],    g_fl[(size_t)NN * HID];
__device__ bf16 g_fcwh[DIM * DIM],  g_fcwl[DIM * DIM];
__device__ bf16 g_w1h[HID * CATD],  g_w1l[HID * CATD];
__device__ bf16 g_w2h[DIM * HID],   g_w2l[DIM * HID];

// ---------------- helpers ----------------
__device__ __forceinline__ uint32_t smem_u32(const void* p) {
    uint32_t a;
    asm("{ .reg .u64 t; cvta.to.shared.u64 t, %1; cvt.u32.u64 %0, t; }"
        : "=r"(a) : "l"(p));
    return a;
}
__device__ __forceinline__ void ldsm4(uint32_t* r, uint32_t addr) {
    asm volatile("ldmatrix.sync.aligned.m8n8.x4.shared.b16 {%0,%1,%2,%3}, [%4];"
                 : "=r"(r[0]), "=r"(r[1]), "=r"(r[2]), "=r"(r[3]) : "r"(addr));
}
__device__ __forceinline__ void mma16816(float* c, const uint32_t* a,
                                         uint32_t b0, uint32_t b1) {
    asm volatile(
        "mma.sync.aligned.m16n8k16.row.col.f32.bf16.bf16.f32 "
        "{%0,%1,%2,%3}, {%4,%5,%6,%7}, {%8,%9}, {%0,%1,%2,%3};"
        : "+f"(c[0]), "+f"(c[1]), "+f"(c[2]), "+f"(c[3])
        : "r"(a[0]), "r"(a[1]), "r"(a[2]), "r"(a[3]), "r"(b0), "r"(b1));
}
__device__ __forceinline__ uint32_t pk_bf2(bf16 a, bf16 b) {
    return (uint32_t)__bfloat16_as_ushort(a) | ((uint32_t)__bfloat16_as_ushort(b) << 16);
}
__device__ __forceinline__ void cpa16(uint32_t dst, const void* src) {
    asm volatile("cp.async.cg.shared.global [%0], [%1], 16;" :: "r"(dst), "l"(src));
}
__device__ __forceinline__ void w16(bf16* hp, bf16* lp, float v) {
    bf16 h = __float2bfloat16(v);
    *hp = h;
    *lp = __float2bfloat16(v - __bfloat162float(h));
}
__device__ __forceinline__ void split4(const float* in, bf16* hi, bf16* lo, size_t i) {
    float4 v = *(const float4*)(in + i);
    bf16 h0 = __float2bfloat16(v.x), h1 = __float2bfloat16(v.y);
    bf16 h2 = __float2bfloat16(v.z), h3 = __float2bfloat16(v.w);
    uint2 H, L;
    H.x = pk_bf2(h0, h1); H.y = pk_bf2(h2, h3);
    L.x = pk_bf2(__float2bfloat16(v.x - __bfloat162float(h0)),
                 __float2bfloat16(v.y - __bfloat162float(h1)));
    L.y = pk_bf2(__float2bfloat16(v.z - __bfloat162float(h2)),
                 __float2bfloat16(v.w - __bfloat162float(h3)));
    *(uint2*)(hi + i) = H;
    *(uint2*)(lo + i) = L;
}

// ---------------- combined fp32 -> bf16 hi/lo split ----------------
#define XF4   ((NN * DIM) / 4)
#define FCF4  ((DIM * DIM) / 4)
#define W1F4  ((HID * CATD) / 4)
#define W2F4  ((DIM * HID) / 4)
#define TOTF4 (XF4 + FCF4 + W1F4 + W2F4)

__global__ void split_all(const float* __restrict__ x, const float* __restrict__ fc_w,
                          const float* __restrict__ w1, const float* __restrict__ w2) {
    int u = blockIdx.x * blockDim.x + threadIdx.x;
    if (u >= TOTF4) return;
    if (u < XF4) {
        split4(x, g_x16h, g_x16l, (size_t)u * 4);
    } else if (u < XF4 + FCF4) {
        split4(fc_w, g_fcwh, g_fcwl, (size_t)(u - XF4) * 4);
    } else if (u < XF4 + FCF4 + W1F4) {
        split4(w1, g_w1h, g_w1l, (size_t)(u - XF4 - FCF4) * 4);
    } else {
        split4(w2, g_w2h, g_w2l, (size_t)(u - XF4 - FCF4 - W1F4) * 4);
    }
}

// ---------------- composite attention weights ----------------
__global__ void combo_w(const float* __restrict__ fc_w, const float* __restrict__ fc_b,
                        const float* __restrict__ au_w, const float* __restrict__ au_b,
                        const float* __restrict__ av_w) {
    int o = blockIdx.x;
    int d = threadIdx.x;
    const float* U = (o < 8) ? (au_w + o * DIM) : (av_w + (o - 8) * DIM);
    float acc = 0.f;
    for (int k = 0; k < DIM; k++)
        acc += U[k] * fc_w[k * DIM + d];
    g_cw[o * DIM + d] = acc;
    if (d == 0) {
        float b = 0.f;
        for (int k = 0; k < DIM; k++) b += U[k] * fc_b[k];
        if (o < 8) b += au_b[o];
        g_cb[o] = b;
    }
}

// ---------------- attention projections from x ----------------
__global__ void __launch_bounds__(256) attn2(const float* __restrict__ x) {
    __shared__ float s_w[16 * DIM];
    __shared__ float s_b[16];
    int t = threadIdx.x, lane = t & 31, warp = t >> 5;
    for (int i = t; i < 16 * DIM; i += 256) s_w[i] = g_cw[i];
    if (t < 16) s_b[t] = g_cb[t];
    __syncthreads();

    float w[16][4];
#pragma unroll
    for (int o = 0; o < 16; o++) {
        float4 ww = *(float4*)&s_w[o * DIM + lane * 4];
        w[o][0] = ww.x; w[o][1] = ww.y; w[o][2] = ww.z; w[o][3] = ww.w;
    }
    int n = blockIdx.x * 8 + warp;
    if (n >= NN) return;

    float4 v = *(const float4*)(x + (size_t)n * DIM + lane * 4);
    float p[16];
#pragma unroll
    for (int o = 0; o < 16; o++)
        p[o] = w[o][0] * v.x + w[o][1] * v.y + w[o][2] * v.z + w[o][3] * v.w;
#pragma unroll
    for (int o = 0; o < 16; o++) {
#pragma unroll
        for (int s2 = 16; s2 > 0; s2 >>= 1)
            p[o] += __shfl_xor_sync(0xffffffffu, p[o], s2);
    }
    float r = p[0];
#pragma unroll
    for (int o = 1; o < 16; o++) r = (lane == o) ? p[o] : r;
    if (lane < 8)       g_su[(size_t)n * 8 + lane]       = r + s_b[lane];
    else if (lane < 16) g_sv[(size_t)n * 8 + (lane - 8)] = r + s_b[lane];
}

// =======================================================================
// bf16x3 mma.sync GEMM — 512 threads / 16 warps (4m x 4n).
// N_TILE=128: warp tile 32x32, 4 stages. N_TILE=256: warp tile 32x64, 3 stages.
// =======================================================================
#define LDK  40
#define ROWB 80
#define ARRA (128 * ROWB)

template <int N_TILE, int STAGES, int ACT, int OUTMODE>
__global__ void __launch_bounds__(512, 1) mma_gemm16(
    const bf16* __restrict__ Ahi, const bf16* __restrict__ Alo,
    const bf16* __restrict__ Bhi, const bf16* __restrict__ Blo,
    const float* __restrict__ bias,
    float* __restrict__ C, int ldc,
    bf16* __restrict__ Chi, bf16* __restrict__ Clo, int ldc16,
    int M, int K, int Nc)
{
    constexpr int ARRB = N_TILE * ROWB;
    constexpr int STGB = 2 * ARRA + 2 * ARRB;
    constexpr int NT   = N_TILE / 32;           // n-tiles per warp (4 or 8)
    constexpr int ROWS = 256 + 2 * N_TILE;      // smem rows per stage
    constexpr int UNITS = ROWS * 4;             // 16B units per stage

    extern __shared__ char sm[];
    float* s_bias = (float*)(sm + STAGES * STGB);

    const int tid  = threadIdx.x;
    const int wid  = tid >> 5;
    const int lane = tid & 31;
    const int m0 = blockIdx.y * 128;
    const int n0 = blockIdx.x * N_TILE;
    const uint32_t sbase = smem_u32(sm);

    if (tid < N_TILE) s_bias[tid] = bias[n0 + tid];

    const int wm = (wid >> 2) * 32;
    const int wn = (wid & 3) * (N_TILE / 4);
    const int lrow = (lane & 7) + ((lane >> 3) & 1) * 8;
    const int lcol = (lane >> 4) * 8;

    float c[2][NT][4];
#pragma unroll
    for (int i = 0; i < 2; i++)
#pragma unroll
        for (int j = 0; j < NT; j++)
#pragma unroll
            for (int r = 0; r < 4; r++) c[i][j][r] = 0.f;

    const int nc = K >> 5;

    auto load_chunk = [&](int ch, int s) {
        const int k0b = ch * 64;
#pragma unroll
        for (int t = 0; t < UNITS / 512; t++) {
            int idx  = tid + t * 512;
            int unit = idx & 3;
            int r    = idx >> 2;
            const char* sp; uint32_t aoff; int grow;
            if (r < 128)        { sp = (const char*)Ahi; aoff = 0;               grow = min(m0 + r, M - 1); }
            else if (r < 256)   { sp = (const char*)Alo; aoff = ARRA;            grow = min(m0 + (r - 128), M - 1); }
            else if (r < 256 + N_TILE) { sp = (const char*)Bhi; aoff = 2 * ARRA; grow = n0 + (r - 256); }
            else                { sp = (const char*)Blo; aoff = 2 * ARRA + ARRB; grow = n0 + (r - 256 - N_TILE); }
            int row = (r < 256) ? (r & 127) : ((r - 256) % N_TILE);
            const char* src = sp + (size_t)grow * (K * 2) + k0b + unit * 16;
            uint32_t dst = sbase + s * STGB + aoff + row * ROWB + unit * 16;
            cpa16(dst, src);
        }
        asm volatile("cp.async.commit_group;" ::: "memory");
    };

#pragma unroll
    for (int i = 0; i < STAGES - 1; i++)
        if (i < nc) load_chunk(i, i);

    for (int ch = 0; ch < nc; ch++) {
        int pend = nc - 1 - ch;
        if (pend > STAGES - 2) pend = STAGES - 2;
        if (pend == 0)      asm volatile("cp.async.wait_group 0;" ::: "memory");
        else if (pend == 1) asm volatile("cp.async.wait_group 1;" ::: "memory");
        else                asm volatile("cp.async.wait_group 2;" ::: "memory");
        __syncthreads();
        if (ch + STAGES - 1 < nc) load_chunk(ch + STAGES - 1, (ch + STAGES - 1) % STAGES);

        const int s = ch % STAGES;
        uint32_t sA_hi = sbase + s * STGB;
        uint32_t sA_lo = sA_hi + ARRA;
        uint32_t sB_hi = sA_lo + ARRA;
        uint32_t sB_lo = sB_hi + ARRB;

#pragma unroll
        for (int ks = 0; ks < 2; ks++) {
            const int kk = ks * 16;
            uint32_t ah[2][4], al[2][4];
#pragma unroll
            for (int mt = 0; mt < 2; mt++) {
                uint32_t off = (uint32_t)((wm + mt * 16 + lrow) * LDK + kk + lcol) * 2;
                ldsm4(ah[mt], sA_hi + off);
                ldsm4(al[mt], sA_lo + off);
            }
#pragma unroll
            for (int p = 0; p < NT / 2; p++) {
                uint32_t off = (uint32_t)((wn + p * 16 + lrow) * LDK + kk + lcol) * 2;
                uint32_t t[4], u[4];
                ldsm4(t, sB_hi + off);
                ldsm4(u, sB_lo + off);
#pragma unroll
                for (int mt = 0; mt < 2; mt++) {
                    mma16816(c[mt][2 * p],     ah[mt], t[0], t[2]);
                    mma16816(c[mt][2 * p],     ah[mt], u[0], u[2]);
                    mma16816(c[mt][2 * p],     al[mt], t[0], t[2]);
                    mma16816(c[mt][2 * p + 1], ah[mt], t[1], t[3]);
                    mma16816(c[mt][2 * p + 1], ah[mt], u[1], u[3]);
                    mma16816(c[mt][2 * p + 1], al[mt], t[1], t[3]);
                }
            }
        }
    }

    const int er = lane >> 2;
    const int ec = (lane & 3) * 2;
#pragma unroll
    for (int mt = 0; mt < 2; mt++) {
#pragma unroll
        for (int half = 0; half < 2; half++) {
            int gm = m0 + wm + mt * 16 + er + half * 8;
            if (gm < M) {
#pragma unroll
                for (int nt = 0; nt < NT; nt++) {
                    int cn = wn + nt * 8 + ec;
                    float v0 = c[mt][nt][half * 2 + 0] + s_bias[cn];
                    float v1 = c[mt][nt][half * 2 + 1] + s_bias[cn + 1];
                    if (ACT == 1) {
                        v0 = 0.5f * v0 * (1.f + erff(v0 * 0.70710678118654752f));
                        v1 = 0.5f * v1 * (1.f + erff(v1 * 0.70710678118654752f));
                    }
                    if (OUTMODE != 1) {
                        float2 o; o.x = v0; o.y = v1;
                        *(float2*)(C + (size_t)gm * ldc + n0 + cn) = o;
                    }
                    if (OUTMODE >= 1) {
                        bf16 h0 = __float2bfloat16(v0);
                        bf16 h1 = __float2bfloat16(v1);
                        uint32_t H = pk_bf2(h0, h1);
                        uint32_t L = pk_bf2(__float2bfloat16(v0 - __bfloat162float(h0)),
                                            __float2bfloat16(v1 - __bfloat162float(h1)));
                        size_t o16 = (size_t)gm * ldc16 + n0 + cn;
                        *(uint32_t*)(Chi + o16) = H;
                        *(uint32_t*)(Clo + o16) = L;
                    }
                }
            }
        }
    }
}

// ---------------- zero init ----------------
__global__ void zero_kernel() {
    int i = blockIdx.x * blockDim.x + threadIdx.x;
    if (i < NN) { g_count[i] = 0; g_outdeg[i] = 0.f; }
}

// ---------------- edge kernel ----------------
__global__ void edge_kernel(const int* __restrict__ src, const int* __restrict__ dst) {
    int e = blockIdx.x * blockDim.x + threadIdx.x;
    if (e >= EE) return;
    int s = src[e], d = dst[e];
    atomicAdd(&g_count[d], 1);
    atomicAdd(&g_outdeg[s], 1.0f);

    float4 u0 = *(const float4*)(g_su + (size_t)s * 8);
    float4 u1 = *(const float4*)(g_su + (size_t)s * 8 + 4);
    float4 v0 = *(const float4*)(g_sv + (size_t)d * 8);
    float4 v1 = *(const float4*)(g_sv + (size_t)d * 8 + 4);
    float r[8] = {u0.x + v0.x, u0.y + v0.y, u0.z + v0.z, u0.w + v0.w,
                  u1.x + v1.x, u1.y + v1.y, u1.z + v1.z, u1.w + v1.w};
#pragma unroll
    for (int h = 0; h < 8; h++) {
        float x = r[h];
        x = (x > 0.f) ? x : 0.2f * x;
        r[h] = expf(x);
    }
    float4* out = (float4*)(g_ex + (size_t)e * 8);
    out[0] = make_float4(r[0], r[1], r[2], r[3]);
    out[1] = make_float4(r[4], r[5], r[6], r[7]);
}

// ---------------- parallel scan ----------------
__global__ void scan_a() {
    __shared__ int sh[1024];
    int tid = threadIdx.x;
    int i = blockIdx.x * 1024 + tid;
    int v = (i < NN) ? g_count[i] : 0;
    sh[tid] = v;
    __syncthreads();
#pragma unroll
    for (int o = 1; o < 1024; o <<= 1) {
        int t2 = (tid >= o) ? sh[tid - o] : 0;
        __syncthreads();
        sh[tid] += t2;
        __syncthreads();
    }
    if (i < NN) g_offsets[i + 1] = sh[tid];
    if (tid == 1023) g_bsum[blockIdx.x] = sh[1023];
}
__global__ void scan_b(int ntiles) {
    if (threadIdx.x == 0) {
        int run = 0;
        for (int i = 0; i < ntiles; i++) { int t = g_bsum[i]; g_bsum[i] = run; run += t; }
    }
}
__global__ void scan_c() {
    int i = blockIdx.x * 1024 + threadIdx.x;
    if (i >= NN) return;
    int base = g_bsum[i >> 10];
    int incl = g_offsets[i + 1];
    int v = g_count[i];
    g_offsets[i + 1] = base + incl;
    g_cursor[i] = base + incl - v;
    if (i == 0) g_offsets[0] = 0;
}

// ---------------- scatter (stores {edge, src}) ----------------
__global__ void scatter_kernel(const int* __restrict__ src, const int* __restrict__ dst) {
    int e = blockIdx.x * blockDim.x + threadIdx.x;
    if (e >= EE) return;
    int pos = atomicAdd(&g_cursor[dst[e]], 1);
    g_csr2[pos] = make_int2(e, src[e]);
}

// ---------------- message: warp-per-node, single pass, no smem ----------------
__global__ void __launch_bounds__(256) message2() {
    int warp = threadIdx.x >> 5, lane = threadIdx.x & 31;
    int n = blockIdx.x * 8 + warp;
    if (n >= NN) return;
    int off = g_offsets[n];
    int deg = g_offsets[n + 1] - off;
    float outdeg_n = g_outdeg[n];
    const int hd = (lane & 1) * 4;

    float a1[4] = {0.f, 0.f, 0.f, 0.f};
    float a2[4] = {0.f, 0.f, 0.f, 0.f};
    float a3[4] = {0.f, 0.f, 0.f, 0.f};
    float dn[4] = {0.f, 0.f, 0.f, 0.f};

    for (int base = 0; base < deg; base += 32) {
        int m = deg - base; if (m > 32) m = 32;
        int2  es = make_int2(0, 0);
        float nl = 0.f;
        if (lane < m) {
            es = g_csr2[off + base + lane];
            nl = rsqrtf(g_outdeg[es.y] * outdeg_n);
        }
        for (int j = 0; j < m; j++) {
            int   s  = __shfl_sync(0xffffffffu, es.y, j);
            int   e  = __shfl_sync(0xffffffffu, es.x, j);
            float nm = __shfl_sync(0xffffffffu, nl, j);
            float4 v = *(const float4*)(g_h + (size_t)s * DIM + lane * 4);
            float4 w = *(const float4*)(g_ex + (size_t)e * 8 + hd);
            a1[0] += v.x * w.x; a1[1] += v.y * w.y; a1[2] += v.z * w.z; a1[3] += v.w * w.w;
            a2[0] += v.x;       a2[1] += v.y;       a2[2] += v.z;       a2[3] += v.w;
            a3[0] += v.x * nm;  a3[1] += v.y * nm;  a3[2] += v.z * nm;  a3[3] += v.w * nm;
            dn[0] += w.x;       dn[1] += w.y;       dn[2] += w.z;       dn[3] += w.w;
        }
    }

    float inv_indeg = 1.f / fmaxf((float)deg, 1.f);
    size_t rowb = (size_t)n * CATD;
#pragma unroll
    for (int q = 0; q < 4; q++) {
        int d = lane * 4 + q;
        float rq = (dn[q] > 0.f) ? (1.f / dn[q]) : 0.f;
        w16(g_cath + rowb + 128 + d, g_catl + rowb + 128 + d, a1[q] * rq);
        w16(g_cath + rowb + 256 + d, g_catl + rowb + 256 + d, a2[q] * inv_indeg);
        w16(g_cath + rowb + 384 + d, g_catl + rowb + 384 + d, a3[q]);
    }
}

// ---------------- launch ----------------
extern "C" void kernel_launch(void* const* d_in, const int* in_sizes, int n_in,
                              void* d_out, int out_size) {
    const float* x    = (const float*)d_in[0];
    const int*   src  = (const int*)  d_in[1];
    const int*   dst  = (const int*)  d_in[2];
    const float* fc_w = (const float*)d_in[3];
    const float* fc_b = (const float*)d_in[4];
    const float* au_w = (const float*)d_in[5];
    const float* au_b = (const float*)d_in[6];
    const float* av_w = (const float*)d_in[7];
    const float* w1   = (const float*)d_in[8];
    const float* b1   = (const float*)d_in[9];
    const float* w2   = (const float*)d_in[10];
    const float* b2   = (const float*)d_in[11];
    float* out = (float*)d_out;

    float* hp;  cudaGetSymbolAddress((void**)&hp, g_h);
    bf16 *x16h, *x16l, *cath, *catl, *fh, *fl, *fcwh, *fcwl, *w1h, *w1l, *w2h, *w2l;
    cudaGetSymbolAddress((void**)&x16h, g_x16h); cudaGetSymbolAddress((void**)&x16l, g_x16l);
    cudaGetSymbolAddress((void**)&cath, g_cath); cudaGetSymbolAddress((void**)&catl, g_catl);
    cudaGetSymbolAddress((void**)&fh,   g_fh);   cudaGetSymbolAddress((void**)&fl,   g_fl);
    cudaGetSymbolAddress((void**)&fcwh, g_fcwh); cudaGetSymbolAddress((void**)&fcwl, g_fcwl);
    cudaGetSymbolAddress((void**)&w1h,  g_w1h);  cudaGetSymbolAddress((void**)&w1l,  g_w1l);
    cudaGetSymbolAddress((void**)&w2h,  g_w2h);  cudaGetSymbolAddress((void**)&w2l,  g_w2l);

    // smem: N128 4-stage: 4*40960+512 = 164352 ; N256 3-stage: 3*61440+1024 = 185344
    const int SM128 = 4 * (2 * ARRA + 2 * 128 * ROWB) + 512;
    const int SM256 = 3 * (2 * ARRA + 2 * 256 * ROWB) + 1024;
    cudaFuncSetAttribute(mma_gemm16<128, 4, 0, 2>, cudaFuncAttributeMaxDynamicSharedMemorySize, SM128);
    cudaFuncSetAttribute(mma_gemm16<256, 3, 1, 1>, cudaFuncAttributeMaxDynamicSharedMemorySize, SM256);
    cudaFuncSetAttribute(mma_gemm16<128, 4, 0, 0>, cudaFuncAttributeMaxDynamicSharedMemorySize, SM128);

    const int MT = (NN + 127) / 128;   // 391
    const int NT2 = (NN + 1023) / 1024; // 49

    // 1-3: zero, split, composite weights
    zero_kernel<<<(NN + 255) / 256, 256>>>();
    split_all<<<(TOTF4 + 255) / 256, 256>>>(x, fc_w, w1, w2);
    combo_w<<<16, 128>>>(fc_w, fc_b, au_w, au_b, av_w);

    // 4. fc GEMM (launch #4 -> ncu capture target)
    mma_gemm16<128, 4, 0, 2><<<dim3(1, MT), 512, SM128>>>(
        x16h, x16l, fcwh, fcwl, fc_b, hp, DIM, cath, catl, CATD, NN, DIM, DIM);

    // 5. su, sv directly from x
    attn2<<<(NN + 7) / 8, 256>>>(x);

    // 6. edge exp + degrees
    edge_kernel<<<(EE + 255) / 256, 256>>>(src, dst);

    // 7. CSR offsets
    scan_a<<<NT2, 1024>>>();
    scan_b<<<1, 32>>>(NT2);
    scan_c<<<NT2, 1024>>>();

    // 8. scatter {e, src}
    scatter_kernel<<<(EE + 255) / 256, 256>>>(src, dst);

    // 9. message (warp per node, single pass)
    message2<<<(NN + 7) / 8, 256>>>();

    // 10. f = gelu(cat @ w1^T + b1)   (128x256 tiles)
    mma_gemm16<256, 3, 1, 1><<<dim3(2, MT), 512, SM256>>>(
        cath, catl, w1h, w1l, b1, nullptr, 0, fh, fl, HID, NN, CATD, HID);

    // 11. out = f @ w2^T + b2
    mma_gemm16<128, 4, 0, 0><<<dim3(1, MT), 512, SM128>>>(
        fh, fl, w2h, w2l, b2, out, DIM, nullptr, nullptr, 0, NN, HID, DIM);
}

// round 13
// speedup vs baseline: 1.5554x; 1.5554x over previous
#include <cuda_runtime.h>
#include <cuda_bf16.h>
#include <math.h>
#include <stdint.h>

#define NN   50000
#define EE   800000
#define DIM  128
#define HH   8
#define HID  512
#define CATD 512

typedef __nv_bfloat16 bf16;

// ---------------- static scratch ----------------
__device__ float g_h[(size_t)NN * DIM];
__device__ float g_su[(size_t)NN * HH];
__device__ float g_sv[(size_t)NN * HH];
__device__ float g_ex[(size_t)EE * HH];
__device__ float g_outdeg[NN];
__device__ int   g_count[NN];
__device__ int   g_offsets[NN + 1];
__device__ int   g_cursor[NN];
__device__ int2  g_csr2[EE];
__device__ int   g_bsum[64];
__device__ float g_cw[16 * DIM];
__device__ float g_cb[16];

// bf16 hi/lo operand storage
__device__ bf16 g_x16h[(size_t)NN * DIM],  g_x16l[(size_t)NN * DIM];
__device__ bf16 g_cath[(size_t)NN * CATD], g_catl[(size_t)NN * CATD];
__device__ bf16 g_fh[(size_t)NN * HID],    g_fl[(size_t)NN * HID];
__device__ bf16 g_fcwh[DIM * DIM],  g_fcwl[DIM * DIM];
__device__ bf16 g_w1h[HID * CATD],  g_w1l[HID * CATD];
__device__ bf16 g_w2h[DIM * HID],   g_w2l[DIM * HID];

// ---------------- helpers ----------------
__device__ __forceinline__ uint32_t smem_u32(const void* p) {
    uint32_t a;
    asm("{ .reg .u64 t; cvta.to.shared.u64 t, %1; cvt.u32.u64 %0, t; }"
        : "=r"(a) : "l"(p));
    return a;
}
__device__ __forceinline__ void ldsm4(uint32_t* r, uint32_t addr) {
    asm volatile("ldmatrix.sync.aligned.m8n8.x4.shared.b16 {%0,%1,%2,%3}, [%4];"
                 : "=r"(r[0]), "=r"(r[1]), "=r"(r[2]), "=r"(r[3]) : "r"(addr));
}
__device__ __forceinline__ void mma16816(float* c, const uint32_t* a, const uint32_t* b) {
    asm volatile(
        "mma.sync.aligned.m16n8k16.row.col.f32.bf16.bf16.f32 "
        "{%0,%1,%2,%3}, {%4,%5,%6,%7}, {%8,%9}, {%0,%1,%2,%3};"
        : "+f"(c[0]), "+f"(c[1]), "+f"(c[2]), "+f"(c[3])
        : "r"(a[0]), "r"(a[1]), "r"(a[2]), "r"(a[3]), "r"(b[0]), "r"(b[1]));
}
__device__ __forceinline__ uint32_t pk_bf2(bf16 a, bf16 b) {
    return (uint32_t)__bfloat16_as_ushort(a) | ((uint32_t)__bfloat16_as_ushort(b) << 16);
}
__device__ __forceinline__ void cpa16(uint32_t dst, const void* src) {
    asm volatile("cp.async.ca.shared.global [%0], [%1], 16;" :: "r"(dst), "l"(src));
}
__device__ __forceinline__ void w16(bf16* hp, bf16* lp, float v) {
    bf16 h = __float2bfloat16(v);
    *hp = h;
    *lp = __float2bfloat16(v - __bfloat162float(h));
}
__device__ __forceinline__ void split4(const float* in, bf16* hi, bf16* lo, size_t i) {
    float4 v = *(const float4*)(in + i);
    bf16 h0 = __float2bfloat16(v.x), h1 = __float2bfloat16(v.y);
    bf16 h2 = __float2bfloat16(v.z), h3 = __float2bfloat16(v.w);
    uint2 H, L;
    H.x = pk_bf2(h0, h1); H.y = pk_bf2(h2, h3);
    L.x = pk_bf2(__float2bfloat16(v.x - __bfloat162float(h0)),
                 __float2bfloat16(v.y - __bfloat162float(h1)));
    L.y = pk_bf2(__float2bfloat16(v.z - __bfloat162float(h2)),
                 __float2bfloat16(v.w - __bfloat162float(h3)));
    *(uint2*)(hi + i) = H;
    *(uint2*)(lo + i) = L;
}

// ---------------- combined fp32 -> bf16 hi/lo split ----------------
#define XF4   ((NN * DIM) / 4)
#define FCF4  ((DIM * DIM) / 4)
#define W1F4  ((HID * CATD) / 4)
#define W2F4  ((DIM * HID) / 4)
#define TOTF4 (XF4 + FCF4 + W1F4 + W2F4)

__global__ void split_all(const float* __restrict__ x, const float* __restrict__ fc_w,
                          const float* __restrict__ w1, const float* __restrict__ w2) {
    int u = blockIdx.x * blockDim.x + threadIdx.x;
    if (u >= TOTF4) return;
    if (u < XF4) {
        split4(x, g_x16h, g_x16l, (size_t)u * 4);
    } else if (u < XF4 + FCF4) {
        split4(fc_w, g_fcwh, g_fcwl, (size_t)(u - XF4) * 4);
    } else if (u < XF4 + FCF4 + W1F4) {
        split4(w1, g_w1h, g_w1l, (size_t)(u - XF4 - FCF4) * 4);
    } else {
        split4(w2, g_w2h, g_w2l, (size_t)(u - XF4 - FCF4 - W1F4) * 4);
    }
}

// ---------------- composite attention weights ----------------
__global__ void combo_w(const float* __restrict__ fc_w, const float* __restrict__ fc_b,
                        const float* __restrict__ au_w, const float* __restrict__ au_b,
                        const float* __restrict__ av_w) {
    int o = blockIdx.x;
    int d = threadIdx.x;
    const float* U = (o < 8) ? (au_w + o * DIM) : (av_w + (o - 8) * DIM);
    float acc = 0.f;
    for (int k = 0; k < DIM; k++)
        acc += U[k] * fc_w[k * DIM + d];
    g_cw[o * DIM + d] = acc;
    if (d == 0) {
        float b = 0.f;
        for (int k = 0; k < DIM; k++) b += U[k] * fc_b[k];
        if (o < 8) b += au_b[o];
        g_cb[o] = b;
    }
}

// ---------------- attention projections from x ----------------
__global__ void __launch_bounds__(256) attn2(const float* __restrict__ x) {
    __shared__ float s_w[16 * DIM];
    __shared__ float s_b[16];
    int t = threadIdx.x, lane = t & 31, warp = t >> 5;
    for (int i = t; i < 16 * DIM; i += 256) s_w[i] = g_cw[i];
    if (t < 16) s_b[t] = g_cb[t];
    __syncthreads();

    float w[16][4];
#pragma unroll
    for (int o = 0; o < 16; o++) {
        float4 ww = *(float4*)&s_w[o * DIM + lane * 4];
        w[o][0] = ww.x; w[o][1] = ww.y; w[o][2] = ww.z; w[o][3] = ww.w;
    }
    int n = blockIdx.x * 8 + warp;
    if (n >= NN) return;

    float4 v = *(const float4*)(x + (size_t)n * DIM + lane * 4);
    float p[16];
#pragma unroll
    for (int o = 0; o < 16; o++)
        p[o] = w[o][0] * v.x + w[o][1] * v.y + w[o][2] * v.z + w[o][3] * v.w;
#pragma unroll
    for (int o = 0; o < 16; o++) {
#pragma unroll
        for (int s2 = 16; s2 > 0; s2 >>= 1)
            p[o] += __shfl_xor_sync(0xffffffffu, p[o], s2);
    }
    float r = p[0];
#pragma unroll
    for (int o = 1; o < 16; o++) r = (lane == o) ? p[o] : r;
    if (lane < 8)       g_su[(size_t)n * 8 + lane]       = r + s_b[lane];
    else if (lane < 16) g_sv[(size_t)n * 8 + (lane - 8)] = r + s_b[lane];
}

// =======================================================================
// bf16x3 mma.sync GEMM — 512 threads / 16 warps (4m x 4n), warp tile 32x32.
// Pre-split hi/lo operands via cp.async(.ca), 3-stage pipeline, K-chunk 32.
// =======================================================================
#define LDK  40
#define ROWB 80
#define ARRB (128 * ROWB)
#define STGB (4 * ARRB)

template <int ACT, int OUTMODE>
__global__ void __launch_bounds__(512, 1) mma_gemm16(
    const bf16* __restrict__ Ahi, const bf16* __restrict__ Alo,
    const bf16* __restrict__ Bhi, const bf16* __restrict__ Blo,
    const float* __restrict__ bias,
    float* __restrict__ C, int ldc,
    bf16* __restrict__ Chi, bf16* __restrict__ Clo, int ldc16,
    int M, int K, int Nc)
{
    extern __shared__ char sm[];
    float* s_bias = (float*)(sm + 3 * STGB);

    const int tid  = threadIdx.x;
    const int wid  = tid >> 5;
    const int lane = tid & 31;
    const int m0 = blockIdx.y * 128;
    const int n0 = blockIdx.x * 128;
    const uint32_t sbase = smem_u32(sm);

    if (tid < 128) s_bias[tid] = bias[n0 + tid];

    const int wm = (wid >> 2) * 32;
    const int wn = (wid & 3) * 32;
    const int lrow = (lane & 7) + ((lane >> 3) & 1) * 8;
    const int lcol = (lane >> 4) * 8;

    float c[2][4][4];
#pragma unroll
    for (int i = 0; i < 2; i++)
#pragma unroll
        for (int j = 0; j < 4; j++)
#pragma unroll
            for (int r = 0; r < 4; r++) c[i][j][r] = 0.f;

    const int nchunks = K >> 5;
    const char* srcs[4] = {(const char*)Ahi, (const char*)Alo,
                           (const char*)Bhi, (const char*)Blo};

    auto load_chunk = [&](int ch, int s) {
        const int k0b = ch * 64;
#pragma unroll
        for (int t = 0; t < 4; t++) {
            int idx  = tid + t * 512;
            int unit = idx & 3;
            int row  = (idx >> 2) & 127;
            int arr  = idx >> 9;
            int grow = (arr < 2) ? min(m0 + row, M - 1) : (n0 + row);
            const char* src = srcs[arr] + (size_t)grow * (K * 2) + k0b + unit * 16;
            uint32_t dst = sbase + s * STGB + arr * ARRB + row * ROWB + unit * 16;
            cpa16(dst, src);
        }
        asm volatile("cp.async.commit_group;" ::: "memory");
    };

    load_chunk(0, 0);
    if (nchunks > 1) load_chunk(1, 1);

    for (int ch = 0; ch < nchunks; ch++) {
        if (ch + 1 < nchunks) {
            asm volatile("cp.async.wait_group 1;" ::: "memory");
        } else {
            asm volatile("cp.async.wait_group 0;" ::: "memory");
        }
        __syncthreads();
        if (ch + 2 < nchunks) load_chunk(ch + 2, (ch + 2) % 3);

        const int s = ch % 3;
        uint32_t sA_hi = sbase + s * STGB;
        uint32_t sA_lo = sA_hi + ARRB;
        uint32_t sB_hi = sA_lo + ARRB;
        uint32_t sB_lo = sB_hi + ARRB;

#pragma unroll
        for (int ks = 0; ks < 2; ks++) {
            const int kk = ks * 16;
            uint32_t ah[2][4], al[2][4], bh[4][2], bl[4][2];
#pragma unroll
            for (int mt = 0; mt < 2; mt++) {
                uint32_t off = (uint32_t)((wm + mt * 16 + lrow) * LDK + kk + lcol) * 2;
                ldsm4(ah[mt], sA_hi + off);
                ldsm4(al[mt], sA_lo + off);
            }
#pragma unroll
            for (int p = 0; p < 2; p++) {
                uint32_t off = (uint32_t)((wn + p * 16 + lrow) * LDK + kk + lcol) * 2;
                uint32_t t[4];
                ldsm4(t, sB_hi + off);
                bh[2 * p][0] = t[0]; bh[2 * p + 1][0] = t[1];
                bh[2 * p][1] = t[2]; bh[2 * p + 1][1] = t[3];
                ldsm4(t, sB_lo + off);
                bl[2 * p][0] = t[0]; bl[2 * p + 1][0] = t[1];
                bl[2 * p][1] = t[2]; bl[2 * p + 1][1] = t[3];
            }
#pragma unroll
            for (int mt = 0; mt < 2; mt++)
#pragma unroll
                for (int nt = 0; nt < 4; nt++) {
                    mma16816(c[mt][nt], ah[mt], bh[nt]);
                    mma16816(c[mt][nt], ah[mt], bl[nt]);
                    mma16816(c[mt][nt], al[mt], bh[nt]);
                }
        }
    }

    const int er = lane >> 2;
    const int ec = (lane & 3) * 2;
#pragma unroll
    for (int mt = 0; mt < 2; mt++) {
#pragma unroll
        for (int half = 0; half < 2; half++) {
            int gm = m0 + wm + mt * 16 + er + half * 8;
            if (gm < M) {
#pragma unroll
                for (int nt = 0; nt < 4; nt++) {
                    int cn = wn + nt * 8 + ec;
                    float v0 = c[mt][nt][half * 2 + 0] + s_bias[cn];
                    float v1 = c[mt][nt][half * 2 + 1] + s_bias[cn + 1];
                    if (ACT == 1) {
                        v0 = 0.5f * v0 * (1.f + erff(v0 * 0.70710678118654752f));
                        v1 = 0.5f * v1 * (1.f + erff(v1 * 0.70710678118654752f));
                    }
                    if (OUTMODE != 1) {
                        float2 o; o.x = v0; o.y = v1;
                        *(float2*)(C + (size_t)gm * ldc + n0 + cn) = o;
                    }
                    if (OUTMODE >= 1) {
                        bf16 h0 = __float2bfloat16(v0);
                        bf16 h1 = __float2bfloat16(v1);
                        uint32_t H = pk_bf2(h0, h1);
                        uint32_t L = pk_bf2(__float2bfloat16(v0 - __bfloat162float(h0)),
                                            __float2bfloat16(v1 - __bfloat162float(h1)));
                        size_t o16 = (size_t)gm * ldc16 + n0 + cn;
                        *(uint32_t*)(Chi + o16) = H;
                        *(uint32_t*)(Clo + o16) = L;
                    }
                }
            }
        }
    }
}

// ---------------- zero init ----------------
__global__ void zero_kernel() {
    int i = blockIdx.x * blockDim.x + threadIdx.x;
    if (i < NN) { g_count[i] = 0; g_outdeg[i] = 0.f; }
}

// ---------------- edge kernel ----------------
__global__ void edge_kernel(const int* __restrict__ src, const int* __restrict__ dst) {
    int e = blockIdx.x * blockDim.x + threadIdx.x;
    if (e >= EE) return;
    int s = src[e], d = dst[e];
    atomicAdd(&g_count[d], 1);
    atomicAdd(&g_outdeg[s], 1.0f);

    float4 u0 = *(const float4*)(g_su + (size_t)s * 8);
    float4 u1 = *(const float4*)(g_su + (size_t)s * 8 + 4);
    float4 v0 = *(const float4*)(g_sv + (size_t)d * 8);
    float4 v1 = *(const float4*)(g_sv + (size_t)d * 8 + 4);
    float r[8] = {u0.x + v0.x, u0.y + v0.y, u0.z + v0.z, u0.w + v0.w,
                  u1.x + v1.x, u1.y + v1.y, u1.z + v1.z, u1.w + v1.w};
#pragma unroll
    for (int h = 0; h < 8; h++) {
        float x = r[h];
        x = (x > 0.f) ? x : 0.2f * x;
        r[h] = expf(x);
    }
    float4* out = (float4*)(g_ex + (size_t)e * 8);
    out[0] = make_float4(r[0], r[1], r[2], r[3]);
    out[1] = make_float4(r[4], r[5], r[6], r[7]);
}

// ---------------- parallel scan ----------------
__global__ void scan_a() {
    __shared__ int sh[1024];
    int tid = threadIdx.x;
    int i = blockIdx.x * 1024 + tid;
    int v = (i < NN) ? g_count[i] : 0;
    sh[tid] = v;
    __syncthreads();
#pragma unroll
    for (int o = 1; o < 1024; o <<= 1) {
        int t2 = (tid >= o) ? sh[tid - o] : 0;
        __syncthreads();
        sh[tid] += t2;
        __syncthreads();
    }
    if (i < NN) g_offsets[i + 1] = sh[tid];
    if (tid == 1023) g_bsum[blockIdx.x] = sh[1023];
}
__global__ void scan_b(int ntiles) {
    if (threadIdx.x == 0) {
        int run = 0;
        for (int i = 0; i < ntiles; i++) { int t = g_bsum[i]; g_bsum[i] = run; run += t; }
    }
}
__global__ void scan_c() {
    int i = blockIdx.x * 1024 + threadIdx.x;
    if (i >= NN) return;
    int base = g_bsum[i >> 10];
    int incl = g_offsets[i + 1];
    int v = g_count[i];
    g_offsets[i + 1] = base + incl;
    g_cursor[i] = base + incl - v;
    if (i == 0) g_offsets[0] = 0;
}

// ---------------- scatter (stores {edge, src}) ----------------
__global__ void scatter_kernel(const int* __restrict__ src, const int* __restrict__ dst) {
    int e = blockIdx.x * blockDim.x + threadIdx.x;
    if (e >= EE) return;
    int pos = atomicAdd(&g_cursor[dst[e]], 1);
    g_csr2[pos] = make_int2(e, src[e]);
}

// ---------------- message: warp-per-node, single pass, no smem ----------------
__global__ void __launch_bounds__(256) message2() {
    int warp = threadIdx.x >> 5, lane = threadIdx.x & 31;
    int n = blockIdx.x * 8 + warp;
    if (n >= NN) return;
    int off = g_offsets[n];
    int deg = g_offsets[n + 1] - off;
    float outdeg_n = g_outdeg[n];
    const int hd = (lane & 1) * 4;

    float a1[4] = {0.f, 0.f, 0.f, 0.f};
    float a2[4] = {0.f, 0.f, 0.f, 0.f};
    float a3[4] = {0.f, 0.f, 0.f, 0.f};
    float dn[4] = {0.f, 0.f, 0.f, 0.f};

    for (int base = 0; base < deg; base += 32) {
        int m = deg - base; if (m > 32) m = 32;
        int2  es = make_int2(0, 0);
        float nl = 0.f;
        if (lane < m) {
            es = g_csr2[off + base + lane];
            nl = rsqrtf(g_outdeg[es.y] * outdeg_n);
        }
        for (int j = 0; j < m; j++) {
            int   s  = __shfl_sync(0xffffffffu, es.y, j);
            int   e  = __shfl_sync(0xffffffffu, es.x, j);
            float nm = __shfl_sync(0xffffffffu, nl, j);
            float4 v = *(const float4*)(g_h + (size_t)s * DIM + lane * 4);
            float4 w = *(const float4*)(g_ex + (size_t)e * 8 + hd);
            a1[0] += v.x * w.x; a1[1] += v.y * w.y; a1[2] += v.z * w.z; a1[3] += v.w * w.w;
            a2[0] += v.x;       a2[1] += v.y;       a2[2] += v.z;       a2[3] += v.w;
            a3[0] += v.x * nm;  a3[1] += v.y * nm;  a3[2] += v.z * nm;  a3[3] += v.w * nm;
            dn[0] += w.x;       dn[1] += w.y;       dn[2] += w.z;       dn[3] += w.w;
        }
    }

    float inv_indeg = 1.f / fmaxf((float)deg, 1.f);
    size_t rowb = (size_t)n * CATD;
#pragma unroll
    for (int q = 0; q < 4; q++) {
        int d = lane * 4 + q;
        float rq = (dn[q] > 0.f) ? (1.f / dn[q]) : 0.f;
        w16(g_cath + rowb + 128 + d, g_catl + rowb + 128 + d, a1[q] * rq);
        w16(g_cath + rowb + 256 + d, g_catl + rowb + 256 + d, a2[q] * inv_indeg);
        w16(g_cath + rowb + 384 + d, g_catl + rowb + 384 + d, a3[q]);
    }
}

// ---------------- launch ----------------
extern "C" void kernel_launch(void* const* d_in, const int* in_sizes, int n_in,
                              void* d_out, int out_size) {
    const float* x    = (const float*)d_in[0];
    const int*   src  = (const int*)  d_in[1];
    const int*   dst  = (const int*)  d_in[2];
    const float* fc_w = (const float*)d_in[3];
    const float* fc_b = (const float*)d_in[4];
    const float* au_w = (const float*)d_in[5];
    const float* au_b = (const float*)d_in[6];
    const float* av_w = (const float*)d_in[7];
    const float* w1   = (const float*)d_in[8];
    const float* b1   = (const float*)d_in[9];
    const float* w2   = (const float*)d_in[10];
    const float* b2   = (const float*)d_in[11];
    float* out = (float*)d_out;

    float* hp;  cudaGetSymbolAddress((void**)&hp, g_h);
    bf16 *x16h, *x16l, *cath, *catl, *fh, *fl, *fcwh, *fcwl, *w1h, *w1l, *w2h, *w2l;
    cudaGetSymbolAddress((void**)&x16h, g_x16h); cudaGetSymbolAddress((void**)&x16l, g_x16l);
    cudaGetSymbolAddress((void**)&cath, g_cath); cudaGetSymbolAddress((void**)&catl, g_catl);
    cudaGetSymbolAddress((void**)&fh,   g_fh);   cudaGetSymbolAddress((void**)&fl,   g_fl);
    cudaGetSymbolAddress((void**)&fcwh, g_fcwh); cudaGetSymbolAddress((void**)&fcwl, g_fcwl);
    cudaGetSymbolAddress((void**)&w1h,  g_w1h);  cudaGetSymbolAddress((void**)&w1l,  g_w1l);
    cudaGetSymbolAddress((void**)&w2h,  g_w2h);  cudaGetSymbolAddress((void**)&w2l,  g_w2l);

    const int SMEM = 3 * STGB + 512;
    cudaFuncSetAttribute(mma_gemm16<0, 2>, cudaFuncAttributeMaxDynamicSharedMemorySize, SMEM);
    cudaFuncSetAttribute(mma_gemm16<1, 1>, cudaFuncAttributeMaxDynamicSharedMemorySize, SMEM);
    cudaFuncSetAttribute(mma_gemm16<0, 0>, cudaFuncAttributeMaxDynamicSharedMemorySize, SMEM);

    const int MT = (NN + 127) / 128;   // 391
    const int NT2 = (NN + 1023) / 1024; // 49

    // Fork/join streams for capture-level overlap. Created fresh per call
    // (kernel_launch runs only a handful of times; graph replays don't re-run it).
    cudaStream_t s2;
    cudaEvent_t ev0, ev1;
    cudaStreamCreateWithFlags(&s2, cudaStreamNonBlocking);
    cudaEventCreateWithFlags(&ev0, cudaEventDisableTiming);
    cudaEventCreateWithFlags(&ev1, cudaEventDisableTiming);

    // 1. zero on main stream, then fork
    zero_kernel<<<(NN + 255) / 256, 256>>>();
    cudaEventRecord(ev0, 0);
    cudaStreamWaitEvent(s2, ev0, 0);

    // Branch B (side stream): combo -> attn2 -> edge -> scan -> scatter
    combo_w<<<16, 128, 0, s2>>>(fc_w, fc_b, au_w, au_b, av_w);
    attn2<<<(NN + 7) / 8, 256, 0, s2>>>(x);
    edge_kernel<<<(EE + 255) / 256, 256, 0, s2>>>(src, dst);
    scan_a<<<NT2, 1024, 0, s2>>>();
    scan_b<<<1, 32, 0, s2>>>(NT2);
    scan_c<<<NT2, 1024, 0, s2>>>();
    scatter_kernel<<<(EE + 255) / 256, 256, 0, s2>>>(src, dst);
    cudaEventRecord(ev1, s2);

    // Branch A (main stream): split -> fc GEMM
    split_all<<<(TOTF4 + 255) / 256, 256>>>(x, fc_w, w1, w2);
    mma_gemm16<0, 2><<<dim3(1, MT), 512, SMEM>>>(
        x16h, x16l, fcwh, fcwl, fc_b, hp, DIM, cath, catl, CATD, NN, DIM, DIM);

    // Join: message needs h (A) + ex/csr/outdeg (B)
    cudaStreamWaitEvent(0, ev1, 0);

    // message (warp per node, single pass)
    message2<<<(NN + 7) / 8, 256>>>();

    // f = gelu(cat @ w1^T + b1)
    mma_gemm16<1, 1><<<dim3(4, MT), 512, SMEM>>>(
        cath, catl, w1h, w1l, b1, nullptr, 0, fh, fl, HID, NN, CATD, HID);

    // out = f @ w2^T + b2
    mma_gemm16<0, 0><<<dim3(1, MT), 512, SMEM>>>(
        fh, fl, w2h, w2l, b2, out, DIM, nullptr, nullptr, 0, NN, HID, DIM);
}